// round 14
// baseline (speedup 1.0000x reference)
#include <cuda_runtime.h>
#include <cuda_bf16.h>
#include <math.h>
#include <stdint.h>

#define DIMD   512
#define HEADS  8
#define HD     64
#define MLPD   2048
#define BATCH  2
#define SEQ    4096
#define BN_TOK 8192   // BATCH*SEQ

// ---------------- scratch (static device arrays; no allocation) -------------
__device__ float g_h  [(size_t)BN_TOK * DIMD];
__device__ float g_q  [(size_t)BN_TOK * DIMD];
__device__ float g_k  [(size_t)BN_TOK * DIMD];
__device__ float g_v  [(size_t)BN_TOK * DIMD];
__device__ float g_att[(size_t)BN_TOK * DIMD];
__device__ float g_xm [(size_t)BN_TOK * DIMD];
__device__ __nv_bfloat16 g_h2h[(size_t)BN_TOK * DIMD];
__device__ __nv_bfloat16 g_h2l[(size_t)BN_TOK * DIMD];
__device__ __nv_bfloat16 g_ffh[(size_t)BN_TOK * MLPD];
__device__ __nv_bfloat16 g_ffl[(size_t)BN_TOK * MLPD];
__device__ __nv_bfloat16 g_w1h[(size_t)MLPD * DIMD], g_w1l[(size_t)MLPD * DIMD];
__device__ __nv_bfloat16 g_w2h[(size_t)DIMD * MLPD], g_w2l[(size_t)DIMD * MLPD];

__device__ __forceinline__ float gelu_exact(float x) {
    return 0.5f * x * (1.0f + erff(x * 0.70710678118654752440f));
}
__device__ __forceinline__ uint32_t pack2_bf16(float a, float b) {
    __nv_bfloat162 t = __floats2bfloat162_rn(a, b);
    return *reinterpret_cast<uint32_t*>(&t);
}
__device__ __forceinline__ void split_bf16(float x, __nv_bfloat16& hi, __nv_bfloat16& lo) {
    hi = __float2bfloat16_rn(x);
    lo = __float2bfloat16_rn(x - __bfloat162float(hi));
}
__device__ __forceinline__ uint32_t smem_u32(const void* p) {
    uint32_t a;
    asm("{ .reg .u64 t; cvta.to.shared.u64 t, %1; cvt.u32.u64 %0, t; }" : "=r"(a) : "l"(p));
    return a;
}

// ---------------- mma.sync -------------------------------------------------
__device__ __forceinline__ void mma_tf32(float* c, const uint32_t* a, const uint32_t* b) {
    asm volatile(
        "mma.sync.aligned.m16n8k8.row.col.f32.tf32.tf32.f32 "
        "{%0,%1,%2,%3},{%4,%5,%6,%7},{%8,%9},{%0,%1,%2,%3};\n"
        : "+f"(c[0]), "+f"(c[1]), "+f"(c[2]), "+f"(c[3])
        : "r"(a[0]), "r"(a[1]), "r"(a[2]), "r"(a[3]), "r"(b[0]), "r"(b[1]));
}
__device__ __forceinline__ void mma_bf16(float* c, const uint32_t* a, const uint32_t* b) {
    asm volatile(
        "mma.sync.aligned.m16n8k16.row.col.f32.bf16.bf16.f32 "
        "{%0,%1,%2,%3},{%4,%5,%6,%7},{%8,%9},{%0,%1,%2,%3};\n"
        : "+f"(c[0]), "+f"(c[1]), "+f"(c[2]), "+f"(c[3])
        : "r"(a[0]), "r"(a[1]), "r"(a[2]), "r"(a[3]), "r"(b[0]), "r"(b[1]));
}

// ---------------- cp.async -------------------------------------------------
__device__ __forceinline__ void cp_async16(uint32_t dst, const void* src) {
    asm volatile("cp.async.cg.shared.global [%0], [%1], 16;" :: "r"(dst), "l"(src));
}
#define CP_COMMIT() asm volatile("cp.async.commit_group;" ::: "memory")
#define CP_WAIT1()  asm volatile("cp.async.wait_group 1;" ::: "memory")

// ---------------- weight transpose + split: W[K][N] -> T_hi/lo[N][K] --------
__global__ void wsplit_kernel(const float* __restrict__ W,
                              __nv_bfloat16* __restrict__ Th,
                              __nv_bfloat16* __restrict__ Tl,
                              int K, int N) {
    __shared__ float tile[32][33];
    int kb = blockIdx.y * 32, nb = blockIdx.x * 32;
    int tx = threadIdx.x, ty = threadIdx.y;   // 32 x 8
    #pragma unroll
    for (int i = 0; i < 32; i += 8)
        tile[ty + i][tx] = W[(size_t)(kb + ty + i) * N + nb + tx];
    __syncthreads();
    #pragma unroll
    for (int i = 0; i < 32; i += 8) {
        float v = tile[tx][ty + i];
        __nv_bfloat16 hi, lo;
        split_bf16(v, hi, lo);
        size_t o = (size_t)(nb + ty + i) * K + kb + tx;
        Th[o] = hi;
        Tl[o] = lo;
    }
}

// ---------------- LayerNorm (fp32 out) --------------------------------------
__global__ void ln_kernel(const float* __restrict__ x, const float* __restrict__ g,
                          const float* __restrict__ be, float* __restrict__ out) {
    int row = blockIdx.x;
    int t = threadIdx.x;
    const float4* xr = (const float4*)(x + (size_t)row * DIMD);
    float4 v = xr[t];
    float s  = v.x + v.y + v.z + v.w;
    float sq = v.x * v.x + v.y * v.y + v.z * v.z + v.w * v.w;
    #pragma unroll
    for (int o = 16; o > 0; o >>= 1) {
        s  += __shfl_xor_sync(0xffffffffu, s,  o);
        sq += __shfl_xor_sync(0xffffffffu, sq, o);
    }
    __shared__ float rs_[4], rq_[4];
    int lane = t & 31, w = t >> 5;
    if (lane == 0) { rs_[w] = s; rq_[w] = sq; }
    __syncthreads();
    s  = rs_[0] + rs_[1] + rs_[2] + rs_[3];
    sq = rq_[0] + rq_[1] + rq_[2] + rq_[3];
    float mu  = s * (1.0f / DIMD);
    float var = sq * (1.0f / DIMD) - mu * mu;
    float rstd = rsqrtf(var + 1e-5f);
    float4 gg = ((const float4*)g)[t];
    float4 bb = ((const float4*)be)[t];
    float4 o4;
    o4.x = (v.x - mu) * rstd * gg.x + bb.x;
    o4.y = (v.y - mu) * rstd * gg.y + bb.y;
    o4.z = (v.z - mu) * rstd * gg.z + bb.z;
    o4.w = (v.w - mu) * rstd * gg.w + bb.w;
    ((float4*)(out + (size_t)row * DIMD))[t] = o4;
}

// ---------------- LayerNorm (bf16 hi/lo out) --------------------------------
__global__ void ln_bf16_kernel(const float* __restrict__ x, const float* __restrict__ g,
                               const float* __restrict__ be,
                               __nv_bfloat16* __restrict__ oh,
                               __nv_bfloat16* __restrict__ ol) {
    int row = blockIdx.x;
    int t = threadIdx.x;
    const float4* xr = (const float4*)(x + (size_t)row * DIMD);
    float4 v = xr[t];
    float s  = v.x + v.y + v.z + v.w;
    float sq = v.x * v.x + v.y * v.y + v.z * v.z + v.w * v.w;
    #pragma unroll
    for (int o = 16; o > 0; o >>= 1) {
        s  += __shfl_xor_sync(0xffffffffu, s,  o);
        sq += __shfl_xor_sync(0xffffffffu, sq, o);
    }
    __shared__ float rs_[4], rq_[4];
    int lane = t & 31, w = t >> 5;
    if (lane == 0) { rs_[w] = s; rq_[w] = sq; }
    __syncthreads();
    s  = rs_[0] + rs_[1] + rs_[2] + rs_[3];
    sq = rq_[0] + rq_[1] + rq_[2] + rq_[3];
    float mu  = s * (1.0f / DIMD);
    float var = sq * (1.0f / DIMD) - mu * mu;
    float rstd = rsqrtf(var + 1e-5f);
    float4 gg = ((const float4*)g)[t];
    float4 bb = ((const float4*)be)[t];
    float4 o4;
    o4.x = (v.x - mu) * rstd * gg.x + bb.x;
    o4.y = (v.y - mu) * rstd * gg.y + bb.y;
    o4.z = (v.z - mu) * rstd * gg.z + bb.z;
    o4.w = (v.w - mu) * rstd * gg.w + bb.w;
    __nv_bfloat16 h0, l0, h1, l1, h2, l2, h3, l3;
    split_bf16(o4.x, h0, l0); split_bf16(o4.y, h1, l1);
    split_bf16(o4.z, h2, l2); split_bf16(o4.w, h3, l3);
    uint2 uh, ul;
    uh.x = pack2_bf16(__bfloat162float(h0), __bfloat162float(h1));
    uh.y = pack2_bf16(__bfloat162float(h2), __bfloat162float(h3));
    ul.x = pack2_bf16(__bfloat162float(l0), __bfloat162float(l1));
    ul.y = pack2_bf16(__bfloat162float(l2), __bfloat162float(l3));
    ((uint2*)(oh + (size_t)row * DIMD))[t] = uh;
    ((uint2*)(ol + (size_t)row * DIMD))[t] = ul;
}

// ---------------- tf32 GEMM, BK=32, cp.async 3-stage ------------------------
// C[M,N] = A[M,K] @ B[K,N] (+epilogue). BM=128, BN=128, BK=32, 256 threads.
// A stage: 128 x 36 f32 (18432B); B stage: 32 x 132 f32 (16896B).
#define TF_AS(st)  ((st) * 18432)
#define TF_BS(st)  (55296 + (st) * 16896)
#define TF_SMEM    (55296 + 3 * 16896)   // 105984

template <int EPI>
__global__ __launch_bounds__(256, 2) void gemm_tf32(
    const float* __restrict__ A, const float* __restrict__ Bm,
    const float* __restrict__ bias, const float* __restrict__ R,
    float* __restrict__ C, int M, int Ncols, int K)
{
    extern __shared__ char dsm[];
    uint32_t sb = smem_u32(dsm);

    int tid = threadIdx.x, wid = tid >> 5, lane = tid & 31;
    int gid = lane >> 2, tg = lane & 3;
    int warpM = wid & 1, warpN = wid >> 1;
    int rowTile = blockIdx.y * 128, colTile = blockIdx.x * 128;

    // A: row ar (0..127), k half ah (0 or 16); 4 float4 per thread
    int ar = tid >> 1, ah = (tid & 1) * 16;
    // B: rows br0+8j (j=0..3), col bc; 4 float4 per thread
    int br0 = tid >> 5, bc = (tid & 31) * 4;

    const float* Ap = A  + (size_t)(rowTile + ar) * K + ah;
    const float* Bp = Bm + (size_t)br0 * Ncols + colTile + bc;
    uint32_t dA = (uint32_t)(ar * 36 + ah) * 4;
    uint32_t dB = (uint32_t)(br0 * 132 + bc) * 4;

    float acc[4][4][4] = {};
    int nIter = K >> 5;

    // prologue: stages 0, 1
    #pragma unroll
    for (int s = 0; s < 2; s++) {
        int k0 = s * 32;
        #pragma unroll
        for (int j = 0; j < 4; j++)
            cp_async16(sb + TF_AS(s) + dA + j * 16, Ap + k0 + j * 4);
        #pragma unroll
        for (int j = 0; j < 4; j++)
            cp_async16(sb + TF_BS(s) + dB + j * 8 * 132 * 4,
                       Bp + (size_t)(k0 + 8 * j) * Ncols);
        CP_COMMIT();
    }

    for (int it = 0; it < nIter; it++) {
        CP_WAIT1();
        __syncthreads();
        int nx = it + 2;
        if (nx < nIter) {
            int st = nx - (nx / 3) * 3;
            int k0 = nx * 32;
            #pragma unroll
            for (int j = 0; j < 4; j++)
                cp_async16(sb + TF_AS(st) + dA + j * 16, Ap + k0 + j * 4);
            #pragma unroll
            for (int j = 0; j < 4; j++)
                cp_async16(sb + TF_BS(st) + dB + j * 8 * 132 * 4,
                           Bp + (size_t)(k0 + 8 * j) * Ncols);
        }
        CP_COMMIT();

        int cur = it - (it / 3) * 3;
        const float* Asc = (const float*)(dsm + TF_AS(cur));
        const float* Bsc = (const float*)(dsm + TF_BS(cur));

        #pragma unroll
        for (int ks = 0; ks < 32; ks += 8) {
            uint32_t af[4][4], bf[4][2];
            #pragma unroll
            for (int mt = 0; mt < 4; mt++) {
                int rb = warpM * 64 + mt * 16;
                af[mt][0] = __float_as_uint(Asc[(rb + gid    ) * 36 + ks + tg    ]);
                af[mt][1] = __float_as_uint(Asc[(rb + gid + 8) * 36 + ks + tg    ]);
                af[mt][2] = __float_as_uint(Asc[(rb + gid    ) * 36 + ks + tg + 4]);
                af[mt][3] = __float_as_uint(Asc[(rb + gid + 8) * 36 + ks + tg + 4]);
            }
            #pragma unroll
            for (int nt = 0; nt < 4; nt++) {
                int nb = warpN * 32 + nt * 8;
                bf[nt][0] = __float_as_uint(Bsc[(ks + tg    ) * 132 + nb + gid]);
                bf[nt][1] = __float_as_uint(Bsc[(ks + tg + 4) * 132 + nb + gid]);
            }
            #pragma unroll
            for (int mt = 0; mt < 4; mt++)
                #pragma unroll
                for (int nt = 0; nt < 4; nt++)
                    mma_tf32(acc[mt][nt], af[mt], bf[nt]);
        }
    }

    #pragma unroll
    for (int mt = 0; mt < 4; mt++) {
        #pragma unroll
        for (int nt = 0; nt < 4; nt++) {
            int col  = colTile + warpN * 32 + nt * 8 + tg * 2;
            int row0 = rowTile + warpM * 64 + mt * 16 + gid;
            int row1 = row0 + 8;
            float2 o0 = make_float2(acc[mt][nt][0], acc[mt][nt][1]);
            float2 o1 = make_float2(acc[mt][nt][2], acc[mt][nt][3]);
            if (EPI >= 1) {
                float b0 = bias[col], b1 = bias[col + 1];
                o0.x += b0; o0.y += b1; o1.x += b0; o1.y += b1;
            }
            if (EPI == 3) {
                const float* r0p = R + (size_t)row0 * Ncols + col;
                const float* r1p = R + (size_t)row1 * Ncols + col;
                o0.x += r0p[0]; o0.y += r0p[1];
                o1.x += r1p[0]; o1.y += r1p[1];
            }
            *(float2*)(C + (size_t)row0 * Ncols + col) = o0;
            *(float2*)(C + (size_t)row1 * Ncols + col) = o1;
        }
    }
}

// ---------------- pre-split bf16x3 GEMM, BK=32, cp.async 2-stage ------------
// A_hi/A_lo bf16 [M][K]; B_hi/B_lo bf16 [N][K]. C = A @ B^T (hh + hl + lh).
// Row = 20 u32 (16 data + 4 pad, 80B, 16-aligned, conflict-free).
// 2 stages, issue-before-wait (prefetch depth = 1 full BK=32 block).
#define BF_AH(st)  ((st) * 10240)
#define BF_AL(st)  (20480 + (st) * 10240)
#define BF_BH(st)  (40960 + (st) * 10240)
#define BF_BL(st)  (61440 + (st) * 10240)
#define BF_SMEM    81920

template <int EPI, int OUTBF>
__global__ __launch_bounds__(256, 2) void gemm_bf16p(
    const __nv_bfloat16* __restrict__ Agh, const __nv_bfloat16* __restrict__ Agl,
    const __nv_bfloat16* __restrict__ Bgh, const __nv_bfloat16* __restrict__ Bgl,
    const float* __restrict__ bias, const float* __restrict__ R,
    float* __restrict__ C, __nv_bfloat16* __restrict__ Ch, __nv_bfloat16* __restrict__ Cl,
    int M, int Ncols, int K)
{
    extern __shared__ char dsm[];
    uint32_t sb = smem_u32(dsm);

    int tid = threadIdx.x, wid = tid >> 5, lane = tid & 31;
    int gid = lane >> 2, tg = lane & 3;
    int warpM = wid & 1, warpN = wid >> 1;
    int rowTile = blockIdx.y * 128, colTile = blockIdx.x * 128;

    int lr = tid >> 1;                 // 0..127 (A row / B col)
    int lc = tid & 1;                  // half: k elems lc*16 .. +15
    uint32_t dOff = (uint32_t)lr * 80 + lc * 32;

    const __nv_bfloat16* ApH = Agh + (size_t)(rowTile + lr) * K + lc * 16;
    const __nv_bfloat16* ApL = Agl + (size_t)(rowTile + lr) * K + lc * 16;
    const __nv_bfloat16* BpH = Bgh + (size_t)(colTile + lr) * K + lc * 16;
    const __nv_bfloat16* BpL = Bgl + (size_t)(colTile + lr) * K + lc * 16;

    float acc[4][4][4] = {};
    int nIter = K >> 5;

    // prologue: stage 0
    {
        cp_async16(sb + BF_AH(0) + dOff,      ApH);
        cp_async16(sb + BF_AH(0) + dOff + 16, ApH + 8);
        cp_async16(sb + BF_AL(0) + dOff,      ApL);
        cp_async16(sb + BF_AL(0) + dOff + 16, ApL + 8);
        cp_async16(sb + BF_BH(0) + dOff,      BpH);
        cp_async16(sb + BF_BH(0) + dOff + 16, BpH + 8);
        cp_async16(sb + BF_BL(0) + dOff,      BpL);
        cp_async16(sb + BF_BL(0) + dOff + 16, BpL + 8);
        CP_COMMIT();
    }

    for (int it = 0; it < nIter; it++) {
        int nx = it + 1;
        if (nx < nIter) {
            int st = nx & 1;
            int k0 = nx * 32;
            cp_async16(sb + BF_AH(st) + dOff,      ApH + k0);
            cp_async16(sb + BF_AH(st) + dOff + 16, ApH + k0 + 8);
            cp_async16(sb + BF_AL(st) + dOff,      ApL + k0);
            cp_async16(sb + BF_AL(st) + dOff + 16, ApL + k0 + 8);
            cp_async16(sb + BF_BH(st) + dOff,      BpH + k0);
            cp_async16(sb + BF_BH(st) + dOff + 16, BpH + k0 + 8);
            cp_async16(sb + BF_BL(st) + dOff,      BpL + k0);
            cp_async16(sb + BF_BL(st) + dOff + 16, BpL + k0 + 8);
        }
        CP_COMMIT();
        CP_WAIT1();
        __syncthreads();

        int cur = it & 1;
        const uint32_t* AhS = (const uint32_t*)(dsm + BF_AH(cur));
        const uint32_t* AlS = (const uint32_t*)(dsm + BF_AL(cur));
        const uint32_t* BhS = (const uint32_t*)(dsm + BF_BH(cur));
        const uint32_t* BlS = (const uint32_t*)(dsm + BF_BL(cur));

        #pragma unroll
        for (int s = 0; s < 2; s++) {          // two k16 steps
            int kp = s * 8;                    // k-pair base
            uint32_t ahr[4][4], alr[4][4], bh[4][2], bl[4][2];
            #pragma unroll
            for (int mt = 0; mt < 4; mt++) {
                int rb = warpM * 64 + mt * 16;
                ahr[mt][0] = AhS[(rb + gid    ) * 20 + kp + tg    ];
                ahr[mt][1] = AhS[(rb + gid + 8) * 20 + kp + tg    ];
                ahr[mt][2] = AhS[(rb + gid    ) * 20 + kp + tg + 4];
                ahr[mt][3] = AhS[(rb + gid + 8) * 20 + kp + tg + 4];
                alr[mt][0] = AlS[(rb + gid    ) * 20 + kp + tg    ];
                alr[mt][1] = AlS[(rb + gid + 8) * 20 + kp + tg    ];
                alr[mt][2] = AlS[(rb + gid    ) * 20 + kp + tg + 4];
                alr[mt][3] = AlS[(rb + gid + 8) * 20 + kp + tg + 4];
            }
            #pragma unroll
            for (int nt = 0; nt < 4; nt++) {
                int nb = warpN * 32 + nt * 8;
                bh[nt][0] = BhS[(nb + gid) * 20 + kp + tg    ];
                bh[nt][1] = BhS[(nb + gid) * 20 + kp + tg + 4];
                bl[nt][0] = BlS[(nb + gid) * 20 + kp + tg    ];
                bl[nt][1] = BlS[(nb + gid) * 20 + kp + tg + 4];
            }
            #pragma unroll
            for (int mt = 0; mt < 4; mt++)
                #pragma unroll
                for (int nt = 0; nt < 4; nt++) {
                    mma_bf16(acc[mt][nt], ahr[mt], bh[nt]);
                    mma_bf16(acc[mt][nt], ahr[mt], bl[nt]);
                    mma_bf16(acc[mt][nt], alr[mt], bh[nt]);
                }
        }
        __syncthreads();
    }

    #pragma unroll
    for (int mt = 0; mt < 4; mt++) {
        #pragma unroll
        for (int nt = 0; nt < 4; nt++) {
            int col  = colTile + warpN * 32 + nt * 8 + tg * 2;
            int row0 = rowTile + warpM * 64 + mt * 16 + gid;
            int row1 = row0 + 8;
            float2 o0 = make_float2(acc[mt][nt][0], acc[mt][nt][1]);
            float2 o1 = make_float2(acc[mt][nt][2], acc[mt][nt][3]);
            if (EPI >= 1) {
                float b0 = bias[col], b1 = bias[col + 1];
                o0.x += b0; o0.y += b1; o1.x += b0; o1.y += b1;
            }
            if (EPI == 2) {
                o0.x = gelu_exact(o0.x); o0.y = gelu_exact(o0.y);
                o1.x = gelu_exact(o1.x); o1.y = gelu_exact(o1.y);
            }
            if (EPI == 3) {
                const float* r0p = R + (size_t)row0 * Ncols + col;
                const float* r1p = R + (size_t)row1 * Ncols + col;
                o0.x += r0p[0]; o0.y += r0p[1];
                o1.x += r1p[0]; o1.y += r1p[1];
            }
            if constexpr (OUTBF) {
                __nv_bfloat16 h0, l0, h1, l1;
                split_bf16(o0.x, h0, l0); split_bf16(o0.y, h1, l1);
                __nv_bfloat162 ph; ph.x = h0; ph.y = h1;
                __nv_bfloat162 pl; pl.x = l0; pl.y = l1;
                *(__nv_bfloat162*)(Ch + (size_t)row0 * Ncols + col) = ph;
                *(__nv_bfloat162*)(Cl + (size_t)row0 * Ncols + col) = pl;
                split_bf16(o1.x, h0, l0); split_bf16(o1.y, h1, l1);
                ph.x = h0; ph.y = h1; pl.x = l0; pl.y = l1;
                *(__nv_bfloat162*)(Ch + (size_t)row1 * Ncols + col) = ph;
                *(__nv_bfloat162*)(Cl + (size_t)row1 * Ncols + col) = pl;
            } else {
                *(float2*)(C + (size_t)row0 * Ncols + col) = o0;
                *(float2*)(C + (size_t)row1 * Ncols + col) = o1;
            }
        }
    }
}

// ---------------- Flash attention (tf32 MMA, online softmax) ----------------
#define FLDS 68
#define FSM_BYTES (3 * 64 * FLDS * 4)

__global__ __launch_bounds__(128, 3) void flash_tf32(
    const float* __restrict__ qp, const float* __restrict__ kp,
    const float* __restrict__ vp, float* __restrict__ att)
{
    extern __shared__ float sm_[];
    float* Ks = sm_;
    float* Vs = sm_ + 64 * FLDS;
    float* Ps = sm_ + 2 * 64 * FLDS;

    int z = blockIdx.y, b = z >> 3, hh = z & 7;
    const float* Q = qp + (size_t)b * SEQ * DIMD + hh * HD;
    const float* K = kp + (size_t)b * SEQ * DIMD + hh * HD;
    const float* V = vp + (size_t)b * SEQ * DIMD + hh * HD;
    float* O = att + (size_t)b * SEQ * DIMD + hh * HD;
    int q0 = blockIdx.x * 64;

    int tid = threadIdx.x, wid = tid >> 5, lane = tid & 31;
    int gid = lane >> 2, tg = lane & 3;
    int rb = wid * 16;

    for (int idx = tid; idx < 64 * 16; idx += 128) {
        int r = idx >> 4, c4 = (idx & 15) * 4;
        float4 a = *(const float4*)(Q + (size_t)(q0 + r) * DIMD + c4);
        a.x *= 0.125f; a.y *= 0.125f; a.z *= 0.125f; a.w *= 0.125f;
        *(float4*)&Ps[r * FLDS + c4] = a;
    }
    __syncthreads();
    uint32_t qf[8][4];
    #pragma unroll
    for (int ki = 0; ki < 8; ki++) {
        int ks = ki * 8;
        qf[ki][0] = __float_as_uint(Ps[(rb + gid    ) * FLDS + ks + tg    ]);
        qf[ki][1] = __float_as_uint(Ps[(rb + gid + 8) * FLDS + ks + tg    ]);
        qf[ki][2] = __float_as_uint(Ps[(rb + gid    ) * FLDS + ks + tg + 4]);
        qf[ki][3] = __float_as_uint(Ps[(rb + gid + 8) * FLDS + ks + tg + 4]);
    }
    __syncthreads();

    float m0 = -1e30f, m1 = -1e30f, l0 = 0.0f, l1 = 0.0f;
    float o[8][4] = {};

    for (int t0 = 0; t0 < SEQ; t0 += 64) {
        for (int idx = tid; idx < 64 * 16; idx += 128) {
            int r = idx >> 4, c4 = (idx & 15) * 4;
            *(float4*)&Ks[r * FLDS + c4] =
                *(const float4*)(K + (size_t)(t0 + r) * DIMD + c4);
            *(float4*)&Vs[r * FLDS + c4] =
                *(const float4*)(V + (size_t)(t0 + r) * DIMD + c4);
        }
        __syncthreads();

        float s[8][4] = {};
        #pragma unroll
        for (int ki = 0; ki < 8; ki++) {
            int ks = ki * 8;
            #pragma unroll
            for (int nt = 0; nt < 8; nt++) {
                uint32_t bf[2];
                bf[0] = __float_as_uint(Ks[(nt * 8 + gid) * FLDS + ks + tg    ]);
                bf[1] = __float_as_uint(Ks[(nt * 8 + gid) * FLDS + ks + tg + 4]);
                mma_tf32(s[nt], qf[ki], bf);
            }
        }

        float tm0 = -1e30f, tm1 = -1e30f;
        #pragma unroll
        for (int nt = 0; nt < 8; nt++) {
            tm0 = fmaxf(tm0, fmaxf(s[nt][0], s[nt][1]));
            tm1 = fmaxf(tm1, fmaxf(s[nt][2], s[nt][3]));
        }
        tm0 = fmaxf(tm0, __shfl_xor_sync(0xffffffffu, tm0, 1));
        tm0 = fmaxf(tm0, __shfl_xor_sync(0xffffffffu, tm0, 2));
        tm1 = fmaxf(tm1, __shfl_xor_sync(0xffffffffu, tm1, 1));
        tm1 = fmaxf(tm1, __shfl_xor_sync(0xffffffffu, tm1, 2));
        float nm0 = fmaxf(m0, tm0), nm1 = fmaxf(m1, tm1);
        float r0 = __expf(m0 - nm0), r1 = __expf(m1 - nm1);
        float sum0 = 0.0f, sum1 = 0.0f;
        #pragma unroll
        for (int nt = 0; nt < 8; nt++) {
            s[nt][0] = __expf(s[nt][0] - nm0);
            s[nt][1] = __expf(s[nt][1] - nm0);
            s[nt][2] = __expf(s[nt][2] - nm1);
            s[nt][3] = __expf(s[nt][3] - nm1);
            sum0 += s[nt][0] + s[nt][1];
            sum1 += s[nt][2] + s[nt][3];
        }
        sum0 += __shfl_xor_sync(0xffffffffu, sum0, 1);
        sum0 += __shfl_xor_sync(0xffffffffu, sum0, 2);
        sum1 += __shfl_xor_sync(0xffffffffu, sum1, 1);
        sum1 += __shfl_xor_sync(0xffffffffu, sum1, 2);
        l0 = l0 * r0 + sum0;
        l1 = l1 * r1 + sum1;
        m0 = nm0; m1 = nm1;
        #pragma unroll
        for (int nt = 0; nt < 8; nt++) {
            o[nt][0] *= r0; o[nt][1] *= r0;
            o[nt][2] *= r1; o[nt][3] *= r1;
        }

        #pragma unroll
        for (int nt = 0; nt < 8; nt++) {
            *(float2*)&Ps[(rb + gid    ) * FLDS + nt * 8 + tg * 2] =
                make_float2(s[nt][0], s[nt][1]);
            *(float2*)&Ps[(rb + gid + 8) * FLDS + nt * 8 + tg * 2] =
                make_float2(s[nt][2], s[nt][3]);
        }
        __syncthreads();

        #pragma unroll
        for (int ki = 0; ki < 8; ki++) {
            int ks = ki * 8;
            uint32_t af[4];
            af[0] = __float_as_uint(Ps[(rb + gid    ) * FLDS + ks + tg    ]);
            af[1] = __float_as_uint(Ps[(rb + gid + 8) * FLDS + ks + tg    ]);
            af[2] = __float_as_uint(Ps[(rb + gid    ) * FLDS + ks + tg + 4]);
            af[3] = __float_as_uint(Ps[(rb + gid + 8) * FLDS + ks + tg + 4]);
            #pragma unroll
            for (int nt = 0; nt < 8; nt++) {
                uint32_t bf[2];
                bf[0] = __float_as_uint(Vs[(ks + tg    ) * FLDS + nt * 8 + gid]);
                bf[1] = __float_as_uint(Vs[(ks + tg + 4) * FLDS + nt * 8 + gid]);
                mma_tf32(o[nt], af, bf);
            }
        }
        __syncthreads();
    }

    float inv0 = 1.0f / l0, inv1 = 1.0f / l1;
    int row0 = q0 + rb + gid, row1 = row0 + 8;
    #pragma unroll
    for (int nt = 0; nt < 8; nt++) {
        int col = nt * 8 + tg * 2;
        *(float2*)(O + (size_t)row0 * DIMD + col) =
            make_float2(o[nt][0] * inv0, o[nt][1] * inv0);
        *(float2*)(O + (size_t)row1 * DIMD + col) =
            make_float2(o[nt][2] * inv1, o[nt][3] * inv1);
    }
}

// ---------------- launch ----------------------------------------------------
extern "C" void kernel_launch(void* const* d_in, const int* in_sizes, int n_in,
                              void* d_out, int out_size) {
    const float* x   = (const float*)d_in[0];
    const float* Wq  = (const float*)d_in[1];
    const float* Wk  = (const float*)d_in[2];
    const float* Wv  = (const float*)d_in[3];
    const float* Wo  = (const float*)d_in[4];
    const float* bo  = (const float*)d_in[5];
    const float* W1  = (const float*)d_in[6];
    const float* b1  = (const float*)d_in[7];
    const float* W2  = (const float*)d_in[8];
    const float* b2  = (const float*)d_in[9];
    const float* g1  = (const float*)d_in[10];
    const float* be1 = (const float*)d_in[11];
    const float* g2  = (const float*)d_in[12];
    const float* be2 = (const float*)d_in[13];
    float* out = (float*)d_out;

    float *h, *q, *k, *v, *att, *xm;
    __nv_bfloat16 *h2h, *h2l, *ffh, *ffl, *w1h, *w1l, *w2h, *w2l;
    cudaGetSymbolAddress((void**)&h,   g_h);
    cudaGetSymbolAddress((void**)&q,   g_q);
    cudaGetSymbolAddress((void**)&k,   g_k);
    cudaGetSymbolAddress((void**)&v,   g_v);
    cudaGetSymbolAddress((void**)&att, g_att);
    cudaGetSymbolAddress((void**)&xm,  g_xm);
    cudaGetSymbolAddress((void**)&h2h, g_h2h);
    cudaGetSymbolAddress((void**)&h2l, g_h2l);
    cudaGetSymbolAddress((void**)&ffh, g_ffh);
    cudaGetSymbolAddress((void**)&ffl, g_ffl);
    cudaGetSymbolAddress((void**)&w1h, g_w1h); cudaGetSymbolAddress((void**)&w1l, g_w1l);
    cudaGetSymbolAddress((void**)&w2h, g_w2h); cudaGetSymbolAddress((void**)&w2l, g_w2l);

    cudaFuncSetAttribute(flash_tf32,
                         cudaFuncAttributeMaxDynamicSharedMemorySize, FSM_BYTES);
    cudaFuncSetAttribute(gemm_tf32<0>,
                         cudaFuncAttributeMaxDynamicSharedMemorySize, TF_SMEM);
    cudaFuncSetAttribute(gemm_tf32<3>,
                         cudaFuncAttributeMaxDynamicSharedMemorySize, TF_SMEM);
    cudaFuncSetAttribute(gemm_bf16p<2, 1>,
                         cudaFuncAttributeMaxDynamicSharedMemorySize, BF_SMEM);
    cudaFuncSetAttribute(gemm_bf16p<3, 0>,
                         cudaFuncAttributeMaxDynamicSharedMemorySize, BF_SMEM);

    dim3 gProj(DIMD / 128, BN_TOK / 128);       // (4, 64)
    dim3 gMlp(MLPD / 128, BN_TOK / 128);        // (16, 64)
    dim3 wg2(MLPD / 32, DIMD / 32), wg3(DIMD / 32, MLPD / 32);
    dim3 wthr(32, 8);

    // 0) weight transpose + bf16 split for MLP weights
    wsplit_kernel<<<wg2, wthr>>>(W1, w1h, w1l, DIMD, MLPD);
    wsplit_kernel<<<wg3, wthr>>>(W2, w2h, w2l, MLPD, DIMD);
    // 1) h = LN(x; g1, be1)
    ln_kernel<<<BN_TOK, 128>>>(x, g1, be1, h);
    // 2) q, k, v projections (single-pass tf32, BK=32 pipelined)
    gemm_tf32<0><<<gProj, 256, TF_SMEM>>>(h, Wq, nullptr, nullptr, q, BN_TOK, DIMD, DIMD);
    gemm_tf32<0><<<gProj, 256, TF_SMEM>>>(h, Wk, nullptr, nullptr, k, BN_TOK, DIMD, DIMD);
    gemm_tf32<0><<<gProj, 256, TF_SMEM>>>(h, Wv, nullptr, nullptr, v, BN_TOK, DIMD, DIMD);
    // 3-5) fused flash attention
    flash_tf32<<<dim3(SEQ / 64, BATCH * HEADS), 128, FSM_BYTES>>>(q, k, v, att);
    // 6) xm = x + att @ Wo + bo
    gemm_tf32<3><<<gProj, 256, TF_SMEM>>>(att, Wo, bo, x, xm, BN_TOK, DIMD, DIMD);
    // 7) h2 = LN(xm; g2, be2) -> pre-split bf16
    ln_bf16_kernel<<<BN_TOK, 128>>>(xm, g2, be2, h2h, h2l);
    // 8) ff = gelu(h2 @ W1 + b1) -> pre-split bf16 (bf16x3, BK=32 pipelined)
    gemm_bf16p<2, 1><<<gMlp, 256, BF_SMEM>>>(h2h, h2l, w1h, w1l, b1, nullptr,
                                             nullptr, ffh, ffl, BN_TOK, MLPD, DIMD);
    // 9) out = xm + ff @ W2 + b2
    gemm_bf16p<3, 0><<<gProj, 256, BF_SMEM>>>(ffh, ffl, w2h, w2l, b2, xm,
                                              out, nullptr, nullptr, BN_TOK, DIMD, MLPD);
}

// round 15
// speedup vs baseline: 1.0099x; 1.0099x over previous
#include <cuda_runtime.h>
#include <cuda_bf16.h>
#include <math.h>
#include <stdint.h>

#define DIMD   512
#define HEADS  8
#define HD     64
#define MLPD   2048
#define BATCH  2
#define SEQ    4096
#define BN_TOK 8192   // BATCH*SEQ

// ---------------- scratch (static device arrays; no allocation) -------------
__device__ float g_q  [(size_t)BN_TOK * DIMD];
__device__ float g_k  [(size_t)BN_TOK * DIMD];
__device__ float g_v  [(size_t)BN_TOK * DIMD];
__device__ float g_xm [(size_t)BN_TOK * DIMD];
__device__ __nv_bfloat16 g_h2h[(size_t)BN_TOK * DIMD];   // LN out split (reused LN1/LN2)
__device__ __nv_bfloat16 g_h2l[(size_t)BN_TOK * DIMD];
__device__ __nv_bfloat16 g_atth[(size_t)BN_TOK * DIMD];  // flash out split
__device__ __nv_bfloat16 g_attl[(size_t)BN_TOK * DIMD];
__device__ __nv_bfloat16 g_ffh[(size_t)BN_TOK * MLPD];
__device__ __nv_bfloat16 g_ffl[(size_t)BN_TOK * MLPD];
// transposed + split weights [N][K]
__device__ __nv_bfloat16 g_wqh[(size_t)DIMD * DIMD], g_wql[(size_t)DIMD * DIMD];
__device__ __nv_bfloat16 g_wkh[(size_t)DIMD * DIMD], g_wkl[(size_t)DIMD * DIMD];
__device__ __nv_bfloat16 g_wvh[(size_t)DIMD * DIMD], g_wvl[(size_t)DIMD * DIMD];
__device__ __nv_bfloat16 g_woh[(size_t)DIMD * DIMD], g_wol[(size_t)DIMD * DIMD];
__device__ __nv_bfloat16 g_w1h[(size_t)MLPD * DIMD], g_w1l[(size_t)MLPD * DIMD];
__device__ __nv_bfloat16 g_w2h[(size_t)DIMD * MLPD], g_w2l[(size_t)DIMD * MLPD];

__device__ __forceinline__ float gelu_exact(float x) {
    return 0.5f * x * (1.0f + erff(x * 0.70710678118654752440f));
}
__device__ __forceinline__ uint32_t pack2_bf16(float a, float b) {
    __nv_bfloat162 t = __floats2bfloat162_rn(a, b);
    return *reinterpret_cast<uint32_t*>(&t);
}
__device__ __forceinline__ void split_bf16(float x, __nv_bfloat16& hi, __nv_bfloat16& lo) {
    hi = __float2bfloat16_rn(x);
    lo = __float2bfloat16_rn(x - __bfloat162float(hi));
}
__device__ __forceinline__ uint32_t smem_u32(const void* p) {
    uint32_t a;
    asm("{ .reg .u64 t; cvta.to.shared.u64 t, %1; cvt.u32.u64 %0, t; }" : "=r"(a) : "l"(p));
    return a;
}

// ---------------- mma.sync -------------------------------------------------
__device__ __forceinline__ void mma_tf32(float* c, const uint32_t* a, const uint32_t* b) {
    asm volatile(
        "mma.sync.aligned.m16n8k8.row.col.f32.tf32.tf32.f32 "
        "{%0,%1,%2,%3},{%4,%5,%6,%7},{%8,%9},{%0,%1,%2,%3};\n"
        : "+f"(c[0]), "+f"(c[1]), "+f"(c[2]), "+f"(c[3])
        : "r"(a[0]), "r"(a[1]), "r"(a[2]), "r"(a[3]), "r"(b[0]), "r"(b[1]));
}
__device__ __forceinline__ void mma_bf16(float* c, const uint32_t* a, const uint32_t* b) {
    asm volatile(
        "mma.sync.aligned.m16n8k16.row.col.f32.bf16.bf16.f32 "
        "{%0,%1,%2,%3},{%4,%5,%6,%7},{%8,%9},{%0,%1,%2,%3};\n"
        : "+f"(c[0]), "+f"(c[1]), "+f"(c[2]), "+f"(c[3])
        : "r"(a[0]), "r"(a[1]), "r"(a[2]), "r"(a[3]), "r"(b[0]), "r"(b[1]));
}
#define LDSM_X4(r0, r1, r2, r3, addr) \
    asm volatile("ldmatrix.sync.aligned.m8n8.x4.shared.b16 {%0,%1,%2,%3}, [%4];" \
                 : "=r"(r0), "=r"(r1), "=r"(r2), "=r"(r3) : "r"(addr))

// ---------------- cp.async -------------------------------------------------
__device__ __forceinline__ void cp_async16(uint32_t dst, const void* src) {
    asm volatile("cp.async.cg.shared.global [%0], [%1], 16;" :: "r"(dst), "l"(src));
}
#define CP_COMMIT() asm volatile("cp.async.commit_group;" ::: "memory")
#define CP_WAIT1()  asm volatile("cp.async.wait_group 1;" ::: "memory")

// ---------------- weight transpose + split: W[K][N] -> T_hi/lo[N][K] --------
__global__ void wsplit_kernel(const float* __restrict__ W,
                              __nv_bfloat16* __restrict__ Th,
                              __nv_bfloat16* __restrict__ Tl,
                              int K, int N) {
    __shared__ float tile[32][33];
    int kb = blockIdx.y * 32, nb = blockIdx.x * 32;
    int tx = threadIdx.x, ty = threadIdx.y;   // 32 x 8
    #pragma unroll
    for (int i = 0; i < 32; i += 8)
        tile[ty + i][tx] = W[(size_t)(kb + ty + i) * N + nb + tx];
    __syncthreads();
    #pragma unroll
    for (int i = 0; i < 32; i += 8) {
        float v = tile[tx][ty + i];
        __nv_bfloat16 hi, lo;
        split_bf16(v, hi, lo);
        size_t o = (size_t)(nb + ty + i) * K + kb + tx;
        Th[o] = hi;
        Tl[o] = lo;
    }
}

// ---------------- LayerNorm (bf16 hi/lo out) --------------------------------
__global__ void ln_bf16_kernel(const float* __restrict__ x, const float* __restrict__ g,
                               const float* __restrict__ be,
                               __nv_bfloat16* __restrict__ oh,
                               __nv_bfloat16* __restrict__ ol) {
    int row = blockIdx.x;
    int t = threadIdx.x;
    const float4* xr = (const float4*)(x + (size_t)row * DIMD);
    float4 v = xr[t];
    float s  = v.x + v.y + v.z + v.w;
    float sq = v.x * v.x + v.y * v.y + v.z * v.z + v.w * v.w;
    #pragma unroll
    for (int o = 16; o > 0; o >>= 1) {
        s  += __shfl_xor_sync(0xffffffffu, s,  o);
        sq += __shfl_xor_sync(0xffffffffu, sq, o);
    }
    __shared__ float rs_[4], rq_[4];
    int lane = t & 31, w = t >> 5;
    if (lane == 0) { rs_[w] = s; rq_[w] = sq; }
    __syncthreads();
    s  = rs_[0] + rs_[1] + rs_[2] + rs_[3];
    sq = rq_[0] + rq_[1] + rq_[2] + rq_[3];
    float mu  = s * (1.0f / DIMD);
    float var = sq * (1.0f / DIMD) - mu * mu;
    float rstd = rsqrtf(var + 1e-5f);
    float4 gg = ((const float4*)g)[t];
    float4 bb = ((const float4*)be)[t];
    float4 o4;
    o4.x = (v.x - mu) * rstd * gg.x + bb.x;
    o4.y = (v.y - mu) * rstd * gg.y + bb.y;
    o4.z = (v.z - mu) * rstd * gg.z + bb.z;
    o4.w = (v.w - mu) * rstd * gg.w + bb.w;
    __nv_bfloat16 h0, l0, h1, l1, h2, l2, h3, l3;
    split_bf16(o4.x, h0, l0); split_bf16(o4.y, h1, l1);
    split_bf16(o4.z, h2, l2); split_bf16(o4.w, h3, l3);
    uint2 uh, ul;
    uh.x = pack2_bf16(__bfloat162float(h0), __bfloat162float(h1));
    uh.y = pack2_bf16(__bfloat162float(h2), __bfloat162float(h3));
    ul.x = pack2_bf16(__bfloat162float(l0), __bfloat162float(l1));
    ul.y = pack2_bf16(__bfloat162float(l2), __bfloat162float(l3));
    ((uint2*)(oh + (size_t)row * DIMD))[t] = uh;
    ((uint2*)(ol + (size_t)row * DIMD))[t] = ul;
}

// ---------------- pre-split bf16x3 GEMM, BK=16, 3-stage, ldmatrix -----------
// A_hi/A_lo bf16 [M][K]; B_hi/B_lo bf16 [N][K]. C = A @ B^T (hh + hl + lh).
// BM=128, BN=128, BK=16, 256 thr. Row = 12 u32 (48B: 32 data + 16 pad).
// Fragments via ldmatrix.m8n8.x4 (stride 48B -> conflict-free phases).
// EPI: 0=none, 1=+bias, 2=+bias,gelu, 3=+bias,+residual; OUTBF: fp32 vs split out.
#define BF_AH(st)  ((st) * 6144)
#define BF_AL(st)  (18432 + (st) * 6144)
#define BF_BH(st)  (36864 + (st) * 6144)
#define BF_BL(st)  (55296 + (st) * 6144)
#define BF_SMEM    73728

template <int EPI, int OUTBF>
__global__ __launch_bounds__(256, 2) void gemm_bf16p(
    const __nv_bfloat16* __restrict__ Agh, const __nv_bfloat16* __restrict__ Agl,
    const __nv_bfloat16* __restrict__ Bgh, const __nv_bfloat16* __restrict__ Bgl,
    const float* __restrict__ bias, const float* __restrict__ R,
    float* __restrict__ C, __nv_bfloat16* __restrict__ Ch, __nv_bfloat16* __restrict__ Cl,
    int M, int Ncols, int K)
{
    extern __shared__ char dsm[];
    uint32_t sb = smem_u32(dsm);

    int tid = threadIdx.x, wid = tid >> 5, lane = tid & 31;
    int gid = lane >> 2, tg = lane & 3;
    int warpM = wid & 1, warpN = wid >> 1;
    int rowTile = blockIdx.y * 128, colTile = blockIdx.x * 128;

    // cp.async fill coords (identical to R12)
    int lr = tid >> 1;
    uint32_t dOff = (uint32_t)lr * 48 + (tid & 1) * 16;
    int lk = (tid & 1) * 8;

    const __nv_bfloat16* ApH = Agh + (size_t)(rowTile + lr) * K + lk;
    const __nv_bfloat16* ApL = Agl + (size_t)(rowTile + lr) * K + lk;
    const __nv_bfloat16* BpH = Bgh + (size_t)(colTile + lr) * K + lk;
    const __nv_bfloat16* BpL = Bgl + (size_t)(colTile + lr) * K + lk;

    // ldmatrix lane-offsets:
    // A x4: m0=rows+0..7 k0 | m1=rows+8..15 k0 | m2=rows+0..7 k8 | m3=rows+8..15 k8
    uint32_t aoffL = (uint32_t)(((lane & 7) + 8 * ((lane >> 3) & 1)) * 48
                               + (lane >> 4) * 16);
    // B x4: m0=rows n0..7 k0 | m1=n0..7 k8 | m2=n8..15 k0 | m3=n8..15 k8
    uint32_t boffL = (uint32_t)((((lane >> 4) & 1) * 8 + (lane & 7)) * 48
                               + ((lane >> 3) & 1) * 16);

    float acc[4][4][4] = {};
    int nIter = K >> 4;

    // prologue: stages 0, 1
    #pragma unroll
    for (int s = 0; s < 2; s++) {
        int k0 = s * 16;
        cp_async16(sb + BF_AH(s) + dOff, ApH + k0);
        cp_async16(sb + BF_AL(s) + dOff, ApL + k0);
        cp_async16(sb + BF_BH(s) + dOff, BpH + k0);
        cp_async16(sb + BF_BL(s) + dOff, BpL + k0);
        CP_COMMIT();
    }

    for (int it = 0; it < nIter; it++) {
        CP_WAIT1();
        __syncthreads();
        int nx = it + 2;
        if (nx < nIter) {
            int st = nx - (nx / 3) * 3;
            int k0 = nx * 16;
            cp_async16(sb + BF_AH(st) + dOff, ApH + k0);
            cp_async16(sb + BF_AL(st) + dOff, ApL + k0);
            cp_async16(sb + BF_BH(st) + dOff, BpH + k0);
            cp_async16(sb + BF_BL(st) + dOff, BpL + k0);
        }
        CP_COMMIT();

        int cur = it - (it / 3) * 3;
        uint32_t sAh = sb + BF_AH(cur), sAl = sb + BF_AL(cur);
        uint32_t sBh = sb + BF_BH(cur), sBl = sb + BF_BL(cur);

        uint32_t ah[4][4], al[4][4], bh[4][2], bl[4][2];
        #pragma unroll
        for (int mt = 0; mt < 4; mt++) {
            uint32_t ab = (uint32_t)(warpM * 64 + mt * 16) * 48 + aoffL;
            LDSM_X4(ah[mt][0], ah[mt][1], ah[mt][2], ah[mt][3], sAh + ab);
            LDSM_X4(al[mt][0], al[mt][1], al[mt][2], al[mt][3], sAl + ab);
        }
        #pragma unroll
        for (int np = 0; np < 2; np++) {
            uint32_t bb = (uint32_t)(warpN * 32 + np * 16) * 48 + boffL;
            LDSM_X4(bh[2*np][0], bh[2*np][1], bh[2*np+1][0], bh[2*np+1][1], sBh + bb);
            LDSM_X4(bl[2*np][0], bl[2*np][1], bl[2*np+1][0], bl[2*np+1][1], sBl + bb);
        }
        #pragma unroll
        for (int mt = 0; mt < 4; mt++)
            #pragma unroll
            for (int nt = 0; nt < 4; nt++) {
                mma_bf16(acc[mt][nt], ah[mt], bh[nt]);
                mma_bf16(acc[mt][nt], ah[mt], bl[nt]);
                mma_bf16(acc[mt][nt], al[mt], bh[nt]);
            }
    }

    #pragma unroll
    for (int mt = 0; mt < 4; mt++) {
        #pragma unroll
        for (int nt = 0; nt < 4; nt++) {
            int col  = colTile + warpN * 32 + nt * 8 + tg * 2;
            int row0 = rowTile + warpM * 64 + mt * 16 + gid;
            int row1 = row0 + 8;
            float2 o0 = make_float2(acc[mt][nt][0], acc[mt][nt][1]);
            float2 o1 = make_float2(acc[mt][nt][2], acc[mt][nt][3]);
            if (EPI >= 1) {
                float b0 = bias[col], b1 = bias[col + 1];
                o0.x += b0; o0.y += b1; o1.x += b0; o1.y += b1;
            }
            if (EPI == 2) {
                o0.x = gelu_exact(o0.x); o0.y = gelu_exact(o0.y);
                o1.x = gelu_exact(o1.x); o1.y = gelu_exact(o1.y);
            }
            if (EPI == 3) {
                const float* r0p = R + (size_t)row0 * Ncols + col;
                const float* r1p = R + (size_t)row1 * Ncols + col;
                o0.x += r0p[0]; o0.y += r0p[1];
                o1.x += r1p[0]; o1.y += r1p[1];
            }
            if constexpr (OUTBF) {
                __nv_bfloat16 h0, l0, h1, l1;
                split_bf16(o0.x, h0, l0); split_bf16(o0.y, h1, l1);
                __nv_bfloat162 ph; ph.x = h0; ph.y = h1;
                __nv_bfloat162 pl; pl.x = l0; pl.y = l1;
                *(__nv_bfloat162*)(Ch + (size_t)row0 * Ncols + col) = ph;
                *(__nv_bfloat162*)(Cl + (size_t)row0 * Ncols + col) = pl;
                split_bf16(o1.x, h0, l0); split_bf16(o1.y, h1, l1);
                ph.x = h0; ph.y = h1; pl.x = l0; pl.y = l1;
                *(__nv_bfloat162*)(Ch + (size_t)row1 * Ncols + col) = ph;
                *(__nv_bfloat162*)(Cl + (size_t)row1 * Ncols + col) = pl;
            } else {
                *(float2*)(C + (size_t)row0 * Ncols + col) = o0;
                *(float2*)(C + (size_t)row1 * Ncols + col) = o1;
            }
        }
    }
}

// ---------------- Flash attention (tf32 MMA, online softmax) ----------------
// Output: pre-split bf16 hi/lo (feeds Wo bf16x3 GEMM).
#define FLDS 68
#define FSM_BYTES (3 * 64 * FLDS * 4)

__global__ __launch_bounds__(128, 3) void flash_tf32(
    const float* __restrict__ qp, const float* __restrict__ kp,
    const float* __restrict__ vp,
    __nv_bfloat16* __restrict__ atth, __nv_bfloat16* __restrict__ attl)
{
    extern __shared__ float sm_[];
    float* Ks = sm_;
    float* Vs = sm_ + 64 * FLDS;
    float* Ps = sm_ + 2 * 64 * FLDS;

    int z = blockIdx.y, b = z >> 3, hh = z & 7;
    const float* Q = qp + (size_t)b * SEQ * DIMD + hh * HD;
    const float* K = kp + (size_t)b * SEQ * DIMD + hh * HD;
    const float* V = vp + (size_t)b * SEQ * DIMD + hh * HD;
    __nv_bfloat16* Oh = atth + (size_t)b * SEQ * DIMD + hh * HD;
    __nv_bfloat16* Ol = attl + (size_t)b * SEQ * DIMD + hh * HD;
    int q0 = blockIdx.x * 64;

    int tid = threadIdx.x, wid = tid >> 5, lane = tid & 31;
    int gid = lane >> 2, tg = lane & 3;
    int rb = wid * 16;

    for (int idx = tid; idx < 64 * 16; idx += 128) {
        int r = idx >> 4, c4 = (idx & 15) * 4;
        float4 a = *(const float4*)(Q + (size_t)(q0 + r) * DIMD + c4);
        a.x *= 0.125f; a.y *= 0.125f; a.z *= 0.125f; a.w *= 0.125f;
        *(float4*)&Ps[r * FLDS + c4] = a;
    }
    __syncthreads();
    uint32_t qf[8][4];
    #pragma unroll
    for (int ki = 0; ki < 8; ki++) {
        int ks = ki * 8;
        qf[ki][0] = __float_as_uint(Ps[(rb + gid    ) * FLDS + ks + tg    ]);
        qf[ki][1] = __float_as_uint(Ps[(rb + gid + 8) * FLDS + ks + tg    ]);
        qf[ki][2] = __float_as_uint(Ps[(rb + gid    ) * FLDS + ks + tg + 4]);
        qf[ki][3] = __float_as_uint(Ps[(rb + gid + 8) * FLDS + ks + tg + 4]);
    }
    __syncthreads();

    float m0 = -1e30f, m1 = -1e30f, l0 = 0.0f, l1 = 0.0f;
    float o[8][4] = {};

    for (int t0 = 0; t0 < SEQ; t0 += 64) {
        for (int idx = tid; idx < 64 * 16; idx += 128) {
            int r = idx >> 4, c4 = (idx & 15) * 4;
            *(float4*)&Ks[r * FLDS + c4] =
                *(const float4*)(K + (size_t)(t0 + r) * DIMD + c4);
            *(float4*)&Vs[r * FLDS + c4] =
                *(const float4*)(V + (size_t)(t0 + r) * DIMD + c4);
        }
        __syncthreads();

        float s[8][4] = {};
        #pragma unroll
        for (int ki = 0; ki < 8; ki++) {
            int ks = ki * 8;
            #pragma unroll
            for (int nt = 0; nt < 8; nt++) {
                uint32_t bf[2];
                bf[0] = __float_as_uint(Ks[(nt * 8 + gid) * FLDS + ks + tg    ]);
                bf[1] = __float_as_uint(Ks[(nt * 8 + gid) * FLDS + ks + tg + 4]);
                mma_tf32(s[nt], qf[ki], bf);
            }
        }

        float tm0 = -1e30f, tm1 = -1e30f;
        #pragma unroll
        for (int nt = 0; nt < 8; nt++) {
            tm0 = fmaxf(tm0, fmaxf(s[nt][0], s[nt][1]));
            tm1 = fmaxf(tm1, fmaxf(s[nt][2], s[nt][3]));
        }
        tm0 = fmaxf(tm0, __shfl_xor_sync(0xffffffffu, tm0, 1));
        tm0 = fmaxf(tm0, __shfl_xor_sync(0xffffffffu, tm0, 2));
        tm1 = fmaxf(tm1, __shfl_xor_sync(0xffffffffu, tm1, 1));
        tm1 = fmaxf(tm1, __shfl_xor_sync(0xffffffffu, tm1, 2));
        float nm0 = fmaxf(m0, tm0), nm1 = fmaxf(m1, tm1);
        float r0 = __expf(m0 - nm0), r1 = __expf(m1 - nm1);
        float sum0 = 0.0f, sum1 = 0.0f;
        #pragma unroll
        for (int nt = 0; nt < 8; nt++) {
            s[nt][0] = __expf(s[nt][0] - nm0);
            s[nt][1] = __expf(s[nt][1] - nm0);
            s[nt][2] = __expf(s[nt][2] - nm1);
            s[nt][3] = __expf(s[nt][3] - nm1);
            sum0 += s[nt][0] + s[nt][1];
            sum1 += s[nt][2] + s[nt][3];
        }
        sum0 += __shfl_xor_sync(0xffffffffu, sum0, 1);
        sum0 += __shfl_xor_sync(0xffffffffu, sum0, 2);
        sum1 += __shfl_xor_sync(0xffffffffu, sum1, 1);
        sum1 += __shfl_xor_sync(0xffffffffu, sum1, 2);
        l0 = l0 * r0 + sum0;
        l1 = l1 * r1 + sum1;
        m0 = nm0; m1 = nm1;
        #pragma unroll
        for (int nt = 0; nt < 8; nt++) {
            o[nt][0] *= r0; o[nt][1] *= r0;
            o[nt][2] *= r1; o[nt][3] *= r1;
        }

        #pragma unroll
        for (int nt = 0; nt < 8; nt++) {
            *(float2*)&Ps[(rb + gid    ) * FLDS + nt * 8 + tg * 2] =
                make_float2(s[nt][0], s[nt][1]);
            *(float2*)&Ps[(rb + gid + 8) * FLDS + nt * 8 + tg * 2] =
                make_float2(s[nt][2], s[nt][3]);
        }
        __syncthreads();

        #pragma unroll
        for (int ki = 0; ki < 8; ki++) {
            int ks = ki * 8;
            uint32_t af[4];
            af[0] = __float_as_uint(Ps[(rb + gid    ) * FLDS + ks + tg    ]);
            af[1] = __float_as_uint(Ps[(rb + gid + 8) * FLDS + ks + tg    ]);
            af[2] = __float_as_uint(Ps[(rb + gid    ) * FLDS + ks + tg + 4]);
            af[3] = __float_as_uint(Ps[(rb + gid + 8) * FLDS + ks + tg + 4]);
            #pragma unroll
            for (int nt = 0; nt < 8; nt++) {
                uint32_t bf[2];
                bf[0] = __float_as_uint(Vs[(ks + tg    ) * FLDS + nt * 8 + gid]);
                bf[1] = __float_as_uint(Vs[(ks + tg + 4) * FLDS + nt * 8 + gid]);
                mma_tf32(o[nt], af, bf);
            }
        }
        __syncthreads();
    }

    float inv0 = 1.0f / l0, inv1 = 1.0f / l1;
    int row0 = q0 + rb + gid, row1 = row0 + 8;
    #pragma unroll
    for (int nt = 0; nt < 8; nt++) {
        int col = nt * 8 + tg * 2;
        float v00 = o[nt][0] * inv0, v01 = o[nt][1] * inv0;
        float v10 = o[nt][2] * inv1, v11 = o[nt][3] * inv1;
        __nv_bfloat16 h0, lo0, h1, lo1;
        split_bf16(v00, h0, lo0); split_bf16(v01, h1, lo1);
        __nv_bfloat162 ph; ph.x = h0; ph.y = h1;
        __nv_bfloat162 pl; pl.x = lo0; pl.y = lo1;
        *(__nv_bfloat162*)(Oh + (size_t)row0 * DIMD + col) = ph;
        *(__nv_bfloat162*)(Ol + (size_t)row0 * DIMD + col) = pl;
        split_bf16(v10, h0, lo0); split_bf16(v11, h1, lo1);
        ph.x = h0; ph.y = h1; pl.x = lo0; pl.y = lo1;
        *(__nv_bfloat162*)(Oh + (size_t)row1 * DIMD + col) = ph;
        *(__nv_bfloat162*)(Ol + (size_t)row1 * DIMD + col) = pl;
    }
}

// ---------------- launch ----------------------------------------------------
extern "C" void kernel_launch(void* const* d_in, const int* in_sizes, int n_in,
                              void* d_out, int out_size) {
    const float* x   = (const float*)d_in[0];
    const float* Wq  = (const float*)d_in[1];
    const float* Wk  = (const float*)d_in[2];
    const float* Wv  = (const float*)d_in[3];
    const float* Wo  = (const float*)d_in[4];
    const float* bo  = (const float*)d_in[5];
    const float* W1  = (const float*)d_in[6];
    const float* b1  = (const float*)d_in[7];
    const float* W2  = (const float*)d_in[8];
    const float* b2  = (const float*)d_in[9];
    const float* g1  = (const float*)d_in[10];
    const float* be1 = (const float*)d_in[11];
    const float* g2  = (const float*)d_in[12];
    const float* be2 = (const float*)d_in[13];
    float* out = (float*)d_out;

    float *q, *k, *v, *xm;
    __nv_bfloat16 *h2h, *h2l, *atth, *attl, *ffh, *ffl;
    __nv_bfloat16 *wqh, *wql, *wkh, *wkl, *wvh, *wvl, *woh, *wol, *w1h, *w1l, *w2h, *w2l;
    cudaGetSymbolAddress((void**)&q,    g_q);
    cudaGetSymbolAddress((void**)&k,    g_k);
    cudaGetSymbolAddress((void**)&v,    g_v);
    cudaGetSymbolAddress((void**)&xm,   g_xm);
    cudaGetSymbolAddress((void**)&h2h,  g_h2h);
    cudaGetSymbolAddress((void**)&h2l,  g_h2l);
    cudaGetSymbolAddress((void**)&atth, g_atth);
    cudaGetSymbolAddress((void**)&attl, g_attl);
    cudaGetSymbolAddress((void**)&ffh,  g_ffh);
    cudaGetSymbolAddress((void**)&ffl,  g_ffl);
    cudaGetSymbolAddress((void**)&wqh, g_wqh); cudaGetSymbolAddress((void**)&wql, g_wql);
    cudaGetSymbolAddress((void**)&wkh, g_wkh); cudaGetSymbolAddress((void**)&wkl, g_wkl);
    cudaGetSymbolAddress((void**)&wvh, g_wvh); cudaGetSymbolAddress((void**)&wvl, g_wvl);
    cudaGetSymbolAddress((void**)&woh, g_woh); cudaGetSymbolAddress((void**)&wol, g_wol);
    cudaGetSymbolAddress((void**)&w1h, g_w1h); cudaGetSymbolAddress((void**)&w1l, g_w1l);
    cudaGetSymbolAddress((void**)&w2h, g_w2h); cudaGetSymbolAddress((void**)&w2l, g_w2l);

    cudaFuncSetAttribute(flash_tf32,
                         cudaFuncAttributeMaxDynamicSharedMemorySize, FSM_BYTES);
    cudaFuncSetAttribute(gemm_bf16p<0, 0>,
                         cudaFuncAttributeMaxDynamicSharedMemorySize, BF_SMEM);
    cudaFuncSetAttribute(gemm_bf16p<3, 0>,
                         cudaFuncAttributeMaxDynamicSharedMemorySize, BF_SMEM);
    cudaFuncSetAttribute(gemm_bf16p<2, 1>,
                         cudaFuncAttributeMaxDynamicSharedMemorySize, BF_SMEM);

    dim3 gProj(DIMD / 128, BN_TOK / 128);       // (4, 64)
    dim3 gMlp(MLPD / 128, BN_TOK / 128);        // (16, 64)
    dim3 wgQ(DIMD / 32, DIMD / 32);
    dim3 wg2(MLPD / 32, DIMD / 32), wg3(DIMD / 32, MLPD / 32);
    dim3 wthr(32, 8);

    // 0) weight transpose + bf16 split (all six weights)
    wsplit_kernel<<<wgQ, wthr>>>(Wq, wqh, wql, DIMD, DIMD);
    wsplit_kernel<<<wgQ, wthr>>>(Wk, wkh, wkl, DIMD, DIMD);
    wsplit_kernel<<<wgQ, wthr>>>(Wv, wvh, wvl, DIMD, DIMD);
    wsplit_kernel<<<wgQ, wthr>>>(Wo, woh, wol, DIMD, DIMD);
    wsplit_kernel<<<wg2, wthr>>>(W1, w1h, w1l, DIMD, MLPD);
    wsplit_kernel<<<wg3, wthr>>>(W2, w2h, w2l, MLPD, DIMD);
    // 1) h = LN(x; g1, be1) -> split
    ln_bf16_kernel<<<BN_TOK, 128>>>(x, g1, be1, h2h, h2l);
    // 2) q, k, v projections (bf16x3, ldmatrix)
    gemm_bf16p<0, 0><<<gProj, 256, BF_SMEM>>>(h2h, h2l, wqh, wql, nullptr, nullptr,
                                              q, nullptr, nullptr, BN_TOK, DIMD, DIMD);
    gemm_bf16p<0, 0><<<gProj, 256, BF_SMEM>>>(h2h, h2l, wkh, wkl, nullptr, nullptr,
                                              k, nullptr, nullptr, BN_TOK, DIMD, DIMD);
    gemm_bf16p<0, 0><<<gProj, 256, BF_SMEM>>>(h2h, h2l, wvh, wvl, nullptr, nullptr,
                                              v, nullptr, nullptr, BN_TOK, DIMD, DIMD);
    // 3-5) fused flash attention -> split att
    flash_tf32<<<dim3(SEQ / 64, BATCH * HEADS), 128, FSM_BYTES>>>(q, k, v, atth, attl);
    // 6) xm = x + att @ Wo + bo
    gemm_bf16p<3, 0><<<gProj, 256, BF_SMEM>>>(atth, attl, woh, wol, bo, x,
                                              xm, nullptr, nullptr, BN_TOK, DIMD, DIMD);
    // 7) h2 = LN(xm; g2, be2) -> split
    ln_bf16_kernel<<<BN_TOK, 128>>>(xm, g2, be2, h2h, h2l);
    // 8) ff = gelu(h2 @ W1 + b1) -> split
    gemm_bf16p<2, 1><<<gMlp, 256, BF_SMEM>>>(h2h, h2l, w1h, w1l, b1, nullptr,
                                             nullptr, ffh, ffl, BN_TOK, MLPD, DIMD);
    // 9) out = xm + ff @ W2 + b2
    gemm_bf16p<3, 0><<<gProj, 256, BF_SMEM>>>(ffh, ffl, w2h, w2l, b2, xm,
                                              out, nullptr, nullptr, BN_TOK, DIMD, MLPD);
}

// round 16
// speedup vs baseline: 1.2642x; 1.2519x over previous
#include <cuda_runtime.h>
#include <cuda_bf16.h>
#include <math.h>
#include <stdint.h>

#define DIMD   512
#define HEADS  8
#define HD     64
#define MLPD   2048
#define BATCH  2
#define SEQ    4096
#define BN_TOK 8192   // BATCH*SEQ
#define QKVD   1536   // 3*DIMD

// ---------------- scratch (static device arrays; no allocation) -------------
__device__ float g_qkv[(size_t)BN_TOK * QKVD];
__device__ float g_xm [(size_t)BN_TOK * DIMD];
__device__ __nv_bfloat16 g_h2h[(size_t)BN_TOK * DIMD];
__device__ __nv_bfloat16 g_h2l[(size_t)BN_TOK * DIMD];
__device__ __nv_bfloat16 g_atth[(size_t)BN_TOK * DIMD];
__device__ __nv_bfloat16 g_attl[(size_t)BN_TOK * DIMD];
__device__ __nv_bfloat16 g_ffh[(size_t)BN_TOK * MLPD];
__device__ __nv_bfloat16 g_ffl[(size_t)BN_TOK * MLPD];
// transposed + split weights [N][K]
__device__ __nv_bfloat16 g_wqkvh[(size_t)QKVD * DIMD], g_wqkvl[(size_t)QKVD * DIMD];
__device__ __nv_bfloat16 g_woh[(size_t)DIMD * DIMD],  g_wol[(size_t)DIMD * DIMD];
__device__ __nv_bfloat16 g_w1h[(size_t)MLPD * DIMD],  g_w1l[(size_t)MLPD * DIMD];
__device__ __nv_bfloat16 g_w2h[(size_t)DIMD * MLPD],  g_w2l[(size_t)DIMD * MLPD];

__device__ __forceinline__ float gelu_exact(float x) {
    return 0.5f * x * (1.0f + erff(x * 0.70710678118654752440f));
}
__device__ __forceinline__ uint32_t pack2_bf16(float a, float b) {
    __nv_bfloat162 t = __floats2bfloat162_rn(a, b);
    return *reinterpret_cast<uint32_t*>(&t);
}
__device__ __forceinline__ void split_bf16(float x, __nv_bfloat16& hi, __nv_bfloat16& lo) {
    hi = __float2bfloat16_rn(x);
    lo = __float2bfloat16_rn(x - __bfloat162float(hi));
}
__device__ __forceinline__ uint32_t smem_u32(const void* p) {
    uint32_t a;
    asm("{ .reg .u64 t; cvta.to.shared.u64 t, %1; cvt.u32.u64 %0, t; }" : "=r"(a) : "l"(p));
    return a;
}

// ---------------- mma.sync -------------------------------------------------
__device__ __forceinline__ void mma_tf32(float* c, const uint32_t* a, const uint32_t* b) {
    asm volatile(
        "mma.sync.aligned.m16n8k8.row.col.f32.tf32.tf32.f32 "
        "{%0,%1,%2,%3},{%4,%5,%6,%7},{%8,%9},{%0,%1,%2,%3};\n"
        : "+f"(c[0]), "+f"(c[1]), "+f"(c[2]), "+f"(c[3])
        : "r"(a[0]), "r"(a[1]), "r"(a[2]), "r"(a[3]), "r"(b[0]), "r"(b[1]));
}
__device__ __forceinline__ void mma_bf16(float* c, const uint32_t* a, const uint32_t* b) {
    asm volatile(
        "mma.sync.aligned.m16n8k16.row.col.f32.bf16.bf16.f32 "
        "{%0,%1,%2,%3},{%4,%5,%6,%7},{%8,%9},{%0,%1,%2,%3};\n"
        : "+f"(c[0]), "+f"(c[1]), "+f"(c[2]), "+f"(c[3])
        : "r"(a[0]), "r"(a[1]), "r"(a[2]), "r"(a[3]), "r"(b[0]), "r"(b[1]));
}
#define LDSM_X4(r0, r1, r2, r3, addr) \
    asm volatile("ldmatrix.sync.aligned.m8n8.x4.shared.b16 {%0,%1,%2,%3}, [%4];" \
                 : "=r"(r0), "=r"(r1), "=r"(r2), "=r"(r3) : "r"(addr))

// ---------------- cp.async -------------------------------------------------
__device__ __forceinline__ void cp_async16(uint32_t dst, const void* src) {
    asm volatile("cp.async.cg.shared.global [%0], [%1], 16;" :: "r"(dst), "l"(src));
}
#define CP_COMMIT() asm volatile("cp.async.commit_group;" ::: "memory")
#define CP_WAIT1()  asm volatile("cp.async.wait_group 1;" ::: "memory")

// ---------------- weight transpose + split: W[K][N] -> T_hi/lo[N][K] --------
__global__ void wsplit_kernel(const float* __restrict__ W,
                              __nv_bfloat16* __restrict__ Th,
                              __nv_bfloat16* __restrict__ Tl,
                              int K, int N) {
    __shared__ float tile[32][33];
    int kb = blockIdx.y * 32, nb = blockIdx.x * 32;
    int tx = threadIdx.x, ty = threadIdx.y;   // 32 x 8
    #pragma unroll
    for (int i = 0; i < 32; i += 8)
        tile[ty + i][tx] = W[(size_t)(kb + ty + i) * N + nb + tx];
    __syncthreads();
    #pragma unroll
    for (int i = 0; i < 32; i += 8) {
        float v = tile[tx][ty + i];
        __nv_bfloat16 hi, lo;
        split_bf16(v, hi, lo);
        size_t o = (size_t)(nb + ty + i) * K + kb + tx;
        Th[o] = hi;
        Tl[o] = lo;
    }
}

// ---------------- LayerNorm (bf16 hi/lo out) --------------------------------
__global__ void ln_bf16_kernel(const float* __restrict__ x, const float* __restrict__ g,
                               const float* __restrict__ be,
                               __nv_bfloat16* __restrict__ oh,
                               __nv_bfloat16* __restrict__ ol) {
    int row = blockIdx.x;
    int t = threadIdx.x;
    const float4* xr = (const float4*)(x + (size_t)row * DIMD);
    float4 v = xr[t];
    float s  = v.x + v.y + v.z + v.w;
    float sq = v.x * v.x + v.y * v.y + v.z * v.z + v.w * v.w;
    #pragma unroll
    for (int o = 16; o > 0; o >>= 1) {
        s  += __shfl_xor_sync(0xffffffffu, s,  o);
        sq += __shfl_xor_sync(0xffffffffu, sq, o);
    }
    __shared__ float rs_[4], rq_[4];
    int lane = t & 31, w = t >> 5;
    if (lane == 0) { rs_[w] = s; rq_[w] = sq; }
    __syncthreads();
    s  = rs_[0] + rs_[1] + rs_[2] + rs_[3];
    sq = rq_[0] + rq_[1] + rq_[2] + rq_[3];
    float mu  = s * (1.0f / DIMD);
    float var = sq * (1.0f / DIMD) - mu * mu;
    float rstd = rsqrtf(var + 1e-5f);
    float4 gg = ((const float4*)g)[t];
    float4 bb = ((const float4*)be)[t];
    float4 o4;
    o4.x = (v.x - mu) * rstd * gg.x + bb.x;
    o4.y = (v.y - mu) * rstd * gg.y + bb.y;
    o4.z = (v.z - mu) * rstd * gg.z + bb.z;
    o4.w = (v.w - mu) * rstd * gg.w + bb.w;
    __nv_bfloat16 h0, l0, h1, l1, h2, l2, h3, l3;
    split_bf16(o4.x, h0, l0); split_bf16(o4.y, h1, l1);
    split_bf16(o4.z, h2, l2); split_bf16(o4.w, h3, l3);
    uint2 uh, ul;
    uh.x = pack2_bf16(__bfloat162float(h0), __bfloat162float(h1));
    uh.y = pack2_bf16(__bfloat162float(h2), __bfloat162float(h3));
    ul.x = pack2_bf16(__bfloat162float(l0), __bfloat162float(l1));
    ul.y = pack2_bf16(__bfloat162float(l2), __bfloat162float(l3));
    ((uint2*)(oh + (size_t)row * DIMD))[t] = uh;
    ((uint2*)(ol + (size_t)row * DIMD))[t] = ul;
}

// ---------------- pre-split bf16 GEMM, BK=16, 3-stage, ldmatrix -------------
// A_hi/A_lo bf16 [M][K]; B_hi/B_lo bf16 [N][K]. C = A @ B^T.
// TERMS: 3 = hh+hl+lh (fp32-accurate), 2 = hh+hl (drops A_lo term).
// BM=128, BN=128, BK=16, 256 thr. Row = 12 u32 (48B: 32 data + 16 pad).
#define BF_AH(st)  ((st) * 6144)
#define BF_AL(st)  (18432 + (st) * 6144)
#define BF_BH(st)  (36864 + (st) * 6144)
#define BF_BL(st)  (55296 + (st) * 6144)
#define BF_SMEM    73728

template <int EPI, int OUTBF, int TERMS>
__global__ __launch_bounds__(256, 2) void gemm_bf16p(
    const __nv_bfloat16* __restrict__ Agh, const __nv_bfloat16* __restrict__ Agl,
    const __nv_bfloat16* __restrict__ Bgh, const __nv_bfloat16* __restrict__ Bgl,
    const float* __restrict__ bias, const float* __restrict__ R,
    float* __restrict__ C, __nv_bfloat16* __restrict__ Ch, __nv_bfloat16* __restrict__ Cl,
    int M, int Ncols, int K)
{
    extern __shared__ char dsm[];
    uint32_t sb = smem_u32(dsm);

    int tid = threadIdx.x, wid = tid >> 5, lane = tid & 31;
    int gid = lane >> 2, tg = lane & 3;
    int warpM = wid & 1, warpN = wid >> 1;
    int rowTile = blockIdx.y * 128, colTile = blockIdx.x * 128;

    int lr = tid >> 1;
    uint32_t dOff = (uint32_t)lr * 48 + (tid & 1) * 16;
    int lk = (tid & 1) * 8;

    const __nv_bfloat16* ApH = Agh + (size_t)(rowTile + lr) * K + lk;
    const __nv_bfloat16* ApL = Agl + (size_t)(rowTile + lr) * K + lk;
    const __nv_bfloat16* BpH = Bgh + (size_t)(colTile + lr) * K + lk;
    const __nv_bfloat16* BpL = Bgl + (size_t)(colTile + lr) * K + lk;

    uint32_t aoffL = (uint32_t)(((lane & 7) + 8 * ((lane >> 3) & 1)) * 48
                               + (lane >> 4) * 16);
    uint32_t boffL = (uint32_t)((((lane >> 4) & 1) * 8 + (lane & 7)) * 48
                               + ((lane >> 3) & 1) * 16);

    float acc[4][4][4] = {};
    int nIter = K >> 4;

    #pragma unroll
    for (int s = 0; s < 2; s++) {
        int k0 = s * 16;
        cp_async16(sb + BF_AH(s) + dOff, ApH + k0);
        if (TERMS == 3) cp_async16(sb + BF_AL(s) + dOff, ApL + k0);
        cp_async16(sb + BF_BH(s) + dOff, BpH + k0);
        cp_async16(sb + BF_BL(s) + dOff, BpL + k0);
        CP_COMMIT();
    }

    for (int it = 0; it < nIter; it++) {
        CP_WAIT1();
        __syncthreads();
        int nx = it + 2;
        if (nx < nIter) {
            int st = nx - (nx / 3) * 3;
            int k0 = nx * 16;
            cp_async16(sb + BF_AH(st) + dOff, ApH + k0);
            if (TERMS == 3) cp_async16(sb + BF_AL(st) + dOff, ApL + k0);
            cp_async16(sb + BF_BH(st) + dOff, BpH + k0);
            cp_async16(sb + BF_BL(st) + dOff, BpL + k0);
        }
        CP_COMMIT();

        int cur = it - (it / 3) * 3;
        uint32_t sAh = sb + BF_AH(cur), sAl = sb + BF_AL(cur);
        uint32_t sBh = sb + BF_BH(cur), sBl = sb + BF_BL(cur);

        uint32_t ah[4][4], al[4][4], bh[4][2], bl[4][2];
        #pragma unroll
        for (int mt = 0; mt < 4; mt++) {
            uint32_t ab = (uint32_t)(warpM * 64 + mt * 16) * 48 + aoffL;
            LDSM_X4(ah[mt][0], ah[mt][1], ah[mt][2], ah[mt][3], sAh + ab);
            if (TERMS == 3)
                LDSM_X4(al[mt][0], al[mt][1], al[mt][2], al[mt][3], sAl + ab);
        }
        #pragma unroll
        for (int np = 0; np < 2; np++) {
            uint32_t bb = (uint32_t)(warpN * 32 + np * 16) * 48 + boffL;
            LDSM_X4(bh[2*np][0], bh[2*np][1], bh[2*np+1][0], bh[2*np+1][1], sBh + bb);
            LDSM_X4(bl[2*np][0], bl[2*np][1], bl[2*np+1][0], bl[2*np+1][1], sBl + bb);
        }
        #pragma unroll
        for (int mt = 0; mt < 4; mt++)
            #pragma unroll
            for (int nt = 0; nt < 4; nt++) {
                mma_bf16(acc[mt][nt], ah[mt], bh[nt]);
                mma_bf16(acc[mt][nt], ah[mt], bl[nt]);
                if (TERMS == 3) mma_bf16(acc[mt][nt], al[mt], bh[nt]);
            }
    }

    #pragma unroll
    for (int mt = 0; mt < 4; mt++) {
        #pragma unroll
        for (int nt = 0; nt < 4; nt++) {
            int col  = colTile + warpN * 32 + nt * 8 + tg * 2;
            int row0 = rowTile + warpM * 64 + mt * 16 + gid;
            int row1 = row0 + 8;
            float2 o0 = make_float2(acc[mt][nt][0], acc[mt][nt][1]);
            float2 o1 = make_float2(acc[mt][nt][2], acc[mt][nt][3]);
            if (EPI >= 1) {
                float b0 = bias[col], b1 = bias[col + 1];
                o0.x += b0; o0.y += b1; o1.x += b0; o1.y += b1;
            }
            if (EPI == 2) {
                o0.x = gelu_exact(o0.x); o0.y = gelu_exact(o0.y);
                o1.x = gelu_exact(o1.x); o1.y = gelu_exact(o1.y);
            }
            if (EPI == 3) {
                const float* r0p = R + (size_t)row0 * Ncols + col;
                const float* r1p = R + (size_t)row1 * Ncols + col;
                o0.x += r0p[0]; o0.y += r0p[1];
                o1.x += r1p[0]; o1.y += r1p[1];
            }
            if constexpr (OUTBF) {
                __nv_bfloat16 h0, l0, h1, l1;
                split_bf16(o0.x, h0, l0); split_bf16(o0.y, h1, l1);
                __nv_bfloat162 ph; ph.x = h0; ph.y = h1;
                __nv_bfloat162 pl; pl.x = l0; pl.y = l1;
                *(__nv_bfloat162*)(Ch + (size_t)row0 * Ncols + col) = ph;
                *(__nv_bfloat162*)(Cl + (size_t)row0 * Ncols + col) = pl;
                split_bf16(o1.x, h0, l0); split_bf16(o1.y, h1, l1);
                ph.x = h0; ph.y = h1; pl.x = l0; pl.y = l1;
                *(__nv_bfloat162*)(Ch + (size_t)row1 * Ncols + col) = ph;
                *(__nv_bfloat162*)(Cl + (size_t)row1 * Ncols + col) = pl;
            } else {
                *(float2*)(C + (size_t)row0 * Ncols + col) = o0;
                *(float2*)(C + (size_t)row1 * Ncols + col) = o1;
            }
        }
    }
}

// ---------------- Flash attention -------------------------------------------
// QK: tf32. PV: bf16 with P taken directly from softmax registers (no smem
// round-trip, no extra syncs); V fragments packed from fp32 Vs on the fly.
// Q/K/V are slices of the fused qkv buffer (row stride QKVD).
#define FLDS 68
#define FSM_BYTES (3 * 64 * FLDS * 4)

__global__ __launch_bounds__(128, 3) void flash_tf32(
    const float* __restrict__ qkv,
    __nv_bfloat16* __restrict__ atth, __nv_bfloat16* __restrict__ attl)
{
    extern __shared__ float sm_[];
    float* Ks = sm_;
    float* Vs = sm_ + 64 * FLDS;
    float* Ps = sm_ + 2 * 64 * FLDS;   // Q staging only

    int z = blockIdx.y, b = z >> 3, hh = z & 7;
    const float* Q = qkv + (size_t)b * SEQ * QKVD + hh * HD;
    const float* K = Q + DIMD;
    const float* V = Q + 2 * DIMD;
    __nv_bfloat16* Oh = atth + (size_t)b * SEQ * DIMD + hh * HD;
    __nv_bfloat16* Ol = attl + (size_t)b * SEQ * DIMD + hh * HD;
    int q0 = blockIdx.x * 64;

    int tid = threadIdx.x, wid = tid >> 5, lane = tid & 31;
    int gid = lane >> 2, tg = lane & 3;
    int rb = wid * 16;

    for (int idx = tid; idx < 64 * 16; idx += 128) {
        int r = idx >> 4, c4 = (idx & 15) * 4;
        float4 a = *(const float4*)(Q + (size_t)(q0 + r) * QKVD + c4);
        a.x *= 0.125f; a.y *= 0.125f; a.z *= 0.125f; a.w *= 0.125f;
        *(float4*)&Ps[r * FLDS + c4] = a;
    }
    __syncthreads();
    uint32_t qf[8][4];
    #pragma unroll
    for (int ki = 0; ki < 8; ki++) {
        int ks = ki * 8;
        qf[ki][0] = __float_as_uint(Ps[(rb + gid    ) * FLDS + ks + tg    ]);
        qf[ki][1] = __float_as_uint(Ps[(rb + gid + 8) * FLDS + ks + tg    ]);
        qf[ki][2] = __float_as_uint(Ps[(rb + gid    ) * FLDS + ks + tg + 4]);
        qf[ki][3] = __float_as_uint(Ps[(rb + gid + 8) * FLDS + ks + tg + 4]);
    }
    __syncthreads();

    float m0 = -1e30f, m1 = -1e30f, l0 = 0.0f, l1 = 0.0f;
    float o[8][4] = {};

    for (int t0 = 0; t0 < SEQ; t0 += 64) {
        for (int idx = tid; idx < 64 * 16; idx += 128) {
            int r = idx >> 4, c4 = (idx & 15) * 4;
            *(float4*)&Ks[r * FLDS + c4] =
                *(const float4*)(K + (size_t)(t0 + r) * QKVD + c4);
            *(float4*)&Vs[r * FLDS + c4] =
                *(const float4*)(V + (size_t)(t0 + r) * QKVD + c4);
        }
        __syncthreads();

        float s[8][4] = {};
        #pragma unroll
        for (int ki = 0; ki < 8; ki++) {
            int ks = ki * 8;
            #pragma unroll
            for (int nt = 0; nt < 8; nt++) {
                uint32_t bf[2];
                bf[0] = __float_as_uint(Ks[(nt * 8 + gid) * FLDS + ks + tg    ]);
                bf[1] = __float_as_uint(Ks[(nt * 8 + gid) * FLDS + ks + tg + 4]);
                mma_tf32(s[nt], qf[ki], bf);
            }
        }

        float tm0 = -1e30f, tm1 = -1e30f;
        #pragma unroll
        for (int nt = 0; nt < 8; nt++) {
            tm0 = fmaxf(tm0, fmaxf(s[nt][0], s[nt][1]));
            tm1 = fmaxf(tm1, fmaxf(s[nt][2], s[nt][3]));
        }
        tm0 = fmaxf(tm0, __shfl_xor_sync(0xffffffffu, tm0, 1));
        tm0 = fmaxf(tm0, __shfl_xor_sync(0xffffffffu, tm0, 2));
        tm1 = fmaxf(tm1, __shfl_xor_sync(0xffffffffu, tm1, 1));
        tm1 = fmaxf(tm1, __shfl_xor_sync(0xffffffffu, tm1, 2));
        float nm0 = fmaxf(m0, tm0), nm1 = fmaxf(m1, tm1);
        float r0 = __expf(m0 - nm0), r1 = __expf(m1 - nm1);
        float sum0 = 0.0f, sum1 = 0.0f;
        #pragma unroll
        for (int nt = 0; nt < 8; nt++) {
            s[nt][0] = __expf(s[nt][0] - nm0);
            s[nt][1] = __expf(s[nt][1] - nm0);
            s[nt][2] = __expf(s[nt][2] - nm1);
            s[nt][3] = __expf(s[nt][3] - nm1);
            sum0 += s[nt][0] + s[nt][1];
            sum1 += s[nt][2] + s[nt][3];
        }
        sum0 += __shfl_xor_sync(0xffffffffu, sum0, 1);
        sum0 += __shfl_xor_sync(0xffffffffu, sum0, 2);
        sum1 += __shfl_xor_sync(0xffffffffu, sum1, 1);
        sum1 += __shfl_xor_sync(0xffffffffu, sum1, 2);
        l0 = l0 * r0 + sum0;
        l1 = l1 * r1 + sum1;
        m0 = nm0; m1 = nm1;
        #pragma unroll
        for (int nt = 0; nt < 8; nt++) {
            o[nt][0] *= r0; o[nt][1] *= r0;
            o[nt][2] *= r1; o[nt][3] *= r1;
        }

        // ---- O += P @ V : P bf16 A-frags from registers; V bf16 from Vs ----
        #pragma unroll
        for (int g = 0; g < 4; g++) {          // k16 windows over 64 keys
            uint32_t af[4];
            af[0] = pack2_bf16(s[2*g    ][0], s[2*g    ][1]);
            af[1] = pack2_bf16(s[2*g    ][2], s[2*g    ][3]);
            af[2] = pack2_bf16(s[2*g + 1][0], s[2*g + 1][1]);
            af[3] = pack2_bf16(s[2*g + 1][2], s[2*g + 1][3]);
            int kb0 = g * 16 + 2 * tg;
            #pragma unroll
            for (int nt = 0; nt < 8; nt++) {
                int n = nt * 8 + gid;
                uint32_t bf[2];
                bf[0] = pack2_bf16(Vs[(kb0    ) * FLDS + n], Vs[(kb0 + 1) * FLDS + n]);
                bf[1] = pack2_bf16(Vs[(kb0 + 8) * FLDS + n], Vs[(kb0 + 9) * FLDS + n]);
                mma_bf16(o[nt], af, bf);
            }
        }
        __syncthreads();
    }

    float inv0 = 1.0f / l0, inv1 = 1.0f / l1;
    int row0 = q0 + rb + gid, row1 = row0 + 8;
    #pragma unroll
    for (int nt = 0; nt < 8; nt++) {
        int col = nt * 8 + tg * 2;
        float v00 = o[nt][0] * inv0, v01 = o[nt][1] * inv0;
        float v10 = o[nt][2] * inv1, v11 = o[nt][3] * inv1;
        __nv_bfloat16 h0, lo0, h1, lo1;
        split_bf16(v00, h0, lo0); split_bf16(v01, h1, lo1);
        __nv_bfloat162 ph; ph.x = h0; ph.y = h1;
        __nv_bfloat162 pl; pl.x = lo0; pl.y = lo1;
        *(__nv_bfloat162*)(Oh + (size_t)row0 * DIMD + col) = ph;
        *(__nv_bfloat162*)(Ol + (size_t)row0 * DIMD + col) = pl;
        split_bf16(v10, h0, lo0); split_bf16(v11, h1, lo1);
        ph.x = h0; ph.y = h1; pl.x = lo0; pl.y = lo1;
        *(__nv_bfloat162*)(Oh + (size_t)row1 * DIMD + col) = ph;
        *(__nv_bfloat162*)(Ol + (size_t)row1 * DIMD + col) = pl;
    }
}

// ---------------- launch ----------------------------------------------------
extern "C" void kernel_launch(void* const* d_in, const int* in_sizes, int n_in,
                              void* d_out, int out_size) {
    const float* x   = (const float*)d_in[0];
    const float* Wq  = (const float*)d_in[1];
    const float* Wk  = (const float*)d_in[2];
    const float* Wv  = (const float*)d_in[3];
    const float* Wo  = (const float*)d_in[4];
    const float* bo  = (const float*)d_in[5];
    const float* W1  = (const float*)d_in[6];
    const float* b1  = (const float*)d_in[7];
    const float* W2  = (const float*)d_in[8];
    const float* b2  = (const float*)d_in[9];
    const float* g1  = (const float*)d_in[10];
    const float* be1 = (const float*)d_in[11];
    const float* g2  = (const float*)d_in[12];
    const float* be2 = (const float*)d_in[13];
    float* out = (float*)d_out;

    float *qkv, *xm;
    __nv_bfloat16 *h2h, *h2l, *atth, *attl, *ffh, *ffl;
    __nv_bfloat16 *wqkvh, *wqkvl, *woh, *wol, *w1h, *w1l, *w2h, *w2l;
    cudaGetSymbolAddress((void**)&qkv,  g_qkv);
    cudaGetSymbolAddress((void**)&xm,   g_xm);
    cudaGetSymbolAddress((void**)&h2h,  g_h2h);
    cudaGetSymbolAddress((void**)&h2l,  g_h2l);
    cudaGetSymbolAddress((void**)&atth, g_atth);
    cudaGetSymbolAddress((void**)&attl, g_attl);
    cudaGetSymbolAddress((void**)&ffh,  g_ffh);
    cudaGetSymbolAddress((void**)&ffl,  g_ffl);
    cudaGetSymbolAddress((void**)&wqkvh, g_wqkvh); cudaGetSymbolAddress((void**)&wqkvl, g_wqkvl);
    cudaGetSymbolAddress((void**)&woh, g_woh); cudaGetSymbolAddress((void**)&wol, g_wol);
    cudaGetSymbolAddress((void**)&w1h, g_w1h); cudaGetSymbolAddress((void**)&w1l, g_w1l);
    cudaGetSymbolAddress((void**)&w2h, g_w2h); cudaGetSymbolAddress((void**)&w2l, g_w2l);

    cudaFuncSetAttribute(flash_tf32,
                         cudaFuncAttributeMaxDynamicSharedMemorySize, FSM_BYTES);
    cudaFuncSetAttribute(gemm_bf16p<0, 0, 2>,
                         cudaFuncAttributeMaxDynamicSharedMemorySize, BF_SMEM);
    cudaFuncSetAttribute(gemm_bf16p<3, 0, 2>,
                         cudaFuncAttributeMaxDynamicSharedMemorySize, BF_SMEM);
    cudaFuncSetAttribute(gemm_bf16p<2, 1, 3>,
                         cudaFuncAttributeMaxDynamicSharedMemorySize, BF_SMEM);
    cudaFuncSetAttribute(gemm_bf16p<3, 0, 3>,
                         cudaFuncAttributeMaxDynamicSharedMemorySize, BF_SMEM);

    dim3 gQKV(QKVD / 128, BN_TOK / 128);        // (12, 64)
    dim3 gProj(DIMD / 128, BN_TOK / 128);       // (4, 64)
    dim3 gMlp(MLPD / 128, BN_TOK / 128);        // (16, 64)
    dim3 wgQ(DIMD / 32, DIMD / 32);
    dim3 wg2(MLPD / 32, DIMD / 32), wg3(DIMD / 32, MLPD / 32);
    dim3 wthr(32, 8);

    // 0) weight transpose + bf16 split (QKV concatenated at row offsets)
    wsplit_kernel<<<wgQ, wthr>>>(Wq, wqkvh,                       wqkvl,                       DIMD, DIMD);
    wsplit_kernel<<<wgQ, wthr>>>(Wk, wqkvh + (size_t)DIMD * DIMD, wqkvl + (size_t)DIMD * DIMD, DIMD, DIMD);
    wsplit_kernel<<<wgQ, wthr>>>(Wv, wqkvh + (size_t)2 * DIMD * DIMD, wqkvl + (size_t)2 * DIMD * DIMD, DIMD, DIMD);
    wsplit_kernel<<<wgQ, wthr>>>(Wo, woh, wol, DIMD, DIMD);
    wsplit_kernel<<<wg2, wthr>>>(W1, w1h, w1l, DIMD, MLPD);
    wsplit_kernel<<<wg3, wthr>>>(W2, w2h, w2l, MLPD, DIMD);
    // 1) h = LN(x; g1, be1) -> split
    ln_bf16_kernel<<<BN_TOK, 128>>>(x, g1, be1, h2h, h2l);
    // 2) fused q|k|v projection (bf16 2-term)
    gemm_bf16p<0, 0, 2><<<gQKV, 256, BF_SMEM>>>(h2h, h2l, wqkvh, wqkvl, nullptr, nullptr,
                                                qkv, nullptr, nullptr, BN_TOK, QKVD, DIMD);
    // 3-5) fused flash attention -> split att
    flash_tf32<<<dim3(SEQ / 64, BATCH * HEADS), 128, FSM_BYTES>>>(qkv, atth, attl);
    // 6) xm = x + att @ Wo + bo  (bf16 2-term)
    gemm_bf16p<3, 0, 2><<<gProj, 256, BF_SMEM>>>(atth, attl, woh, wol, bo, x,
                                                 xm, nullptr, nullptr, BN_TOK, DIMD, DIMD);
    // 7) h2 = LN(xm; g2, be2) -> split
    ln_bf16_kernel<<<BN_TOK, 128>>>(xm, g2, be2, h2h, h2l);
    // 8) ff = gelu(h2 @ W1 + b1) -> split  (bf16x3)
    gemm_bf16p<2, 1, 3><<<gMlp, 256, BF_SMEM>>>(h2h, h2l, w1h, w1l, b1, nullptr,
                                                nullptr, ffh, ffl, BN_TOK, MLPD, DIMD);
    // 9) out = xm + ff @ W2 + b2  (bf16x3)
    gemm_bf16p<3, 0, 3><<<gProj, 256, BF_SMEM>>>(ffh, ffl, w2h, w2l, b2, xm,
                                                 out, nullptr, nullptr, BN_TOK, DIMD, MLPD);
}